// round 10
// baseline (speedup 1.0000x reference)
#include <cuda_runtime.h>
#include <cuda_bf16.h>

// Shapes: batch_x [32,4096,128] -> N=4096 rows x 4096 (I=64 patches, L=64)
//         pred    [32,1024,128] -> N=4096 rows x 1024 (J=16 patches, L=64)
//
// Math (sum_l q_jl = 1 => lse_i cancels in softmax over j):
//   dot_ij = q_j . x_i (raw x);  u_ij = ne_j - dot_ij  (ne_j = sum q log q)
//   loss = mean_n [ sum_i ( sum_j softmax_j(u_ij)*u_ij + lse_i ) ]
//
// CTA = 128 threads = 2 rows x 2 warps/row. Lane (g=lane&15, h=lane>>4) owns
// patches p0=32*wir+g and p1=p0+16, j-half h. q transposed [l][j] stride 20,
// loaded as ulonglong2 broadcast pairs; amortized over TWO patches (16 FFMA2
// per 2 q-LDS). XSTR=72 puts x-LDS at the 4-phase minimum.
#define NROWS 4096
#define SEQ   4096
#define PREDL 1024
#define RPC   2
#define NCTAS (NROWS / RPC)   // 2048
#define XSTR  72
#define QSTR  20

__device__ float g_blk_sum[NCTAS];
__device__ unsigned g_ctr = 0;

__device__ __forceinline__ unsigned long long pk2(float a, float b) {
    unsigned long long r;
    asm("mov.b64 %0, {%1, %2};" : "=l"(r) : "f"(a), "f"(b));
    return r;
}
__device__ __forceinline__ void fma2(unsigned long long& d,
                                     unsigned long long a, unsigned long long b) {
    asm("fma.rn.f32x2 %0, %1, %2, %0;" : "+l"(d) : "l"(a), "l"(b));
}
__device__ __forceinline__ float2 unpk2(unsigned long long v) {
    float2 r;
    asm("mov.b64 {%0, %1}, %2;" : "=f"(r.x), "=f"(r.y) : "l"(v));
    return r;
}

__global__ __launch_bounds__(128, 5)
void kl_fused_kernel(const float* __restrict__ x, const float* __restrict__ pred,
                     float* __restrict__ out) {
    __shared__ __align__(16) float xs[RPC][64 * XSTR];   // 36.9KB
    __shared__ __align__(16) float qt[RPC][64 * QSTR];   // 10.2KB
    __shared__ __align__(16) float ne_s[RPC][16];
    __shared__ float red[4];
    __shared__ int   is_last_sh;

    const int t     = threadIdx.x;
    const int warp  = t >> 5;
    const int lane  = t & 31;
    const int r     = t >> 6;      // row within CTA
    const int tid64 = t & 63;      // thread within row group
    const int n     = blockIdx.x * RPC + r;

    float lse_part = 0.f;

    // ---- Phase A: coalesced x copy into padded smem + per-patch lse ----
    {
        const float4* x4 = (const float4*)(x + (size_t)n * SEQ);
        float* xb = xs[r];
        #pragma unroll
        for (int k = 0; k < 16; k++) {
            const int idx   = tid64 + 64 * k;
            float4 v = x4[idx];
            const int patch = idx >> 4;
            const int pos   = idx & 15;
            ((float4*)(xb + patch * XSTR))[pos] = v;
            // naive expsum (inputs ~N(0,1), fp32-safe; validated 1.2e-7)
            float E = __expf(v.x) + __expf(v.y) + __expf(v.z) + __expf(v.w);
            #pragma unroll
            for (int o = 8; o; o >>= 1) E += __shfl_xor_sync(0xffffffffu, E, o);
            if ((lane & 15) == 0) lse_part += __logf(E);
        }
    }

    // ---- Phase B: pred row -> q (smem, transposed [l][j]) + ne_j ----
    {
        const float4* pr4 = (const float4*)(pred + (size_t)n * PREDL);
        float* qb = qt[r];
        #pragma unroll
        for (int k = 0; k < 4; k++) {
            const int idx = tid64 + 64 * k;
            float4 v = pr4[idx];
            const int j  = idx >> 4;
            const int l0 = 4 * (idx & 15);
            float e0 = __expf(v.x), e1 = __expf(v.y);
            float e2 = __expf(v.z), e3 = __expf(v.w);
            float E = e0 + e1 + e2 + e3;
            float S = e0 * v.x + e1 * v.y + e2 * v.z + e3 * v.w;
            #pragma unroll
            for (int o = 8; o; o >>= 1) {
                E += __shfl_xor_sync(0xffffffffu, E, o);
                S += __shfl_xor_sync(0xffffffffu, S, o);
            }
            float rinv = __frcp_rn(E);
            qb[(l0 + 0) * QSTR + j] = e0 * rinv;
            qb[(l0 + 1) * QSTR + j] = e1 * rinv;
            qb[(l0 + 2) * QSTR + j] = e2 * rinv;
            qb[(l0 + 3) * QSTR + j] = e3 * rinv;
            if ((lane & 15) == 0) ne_s[r][j] = S * rinv - __logf(E);
        }
    }
    __syncthreads();

    // ---- Phase C: 2 patches per lane, half-j, q amortized over both ----
    const int g   = lane & 15;
    const int h   = lane >> 4;
    const int wir = warp & 1;
    const int p0  = 32 * wir + g;
    const int p1  = p0 + 16;

    unsigned long long accA[4], accB[4];
    #pragma unroll
    for (int m = 0; m < 4; m++) { accA[m] = 0ull; accB[m] = 0ull; }
    {
        const float* qb = qt[r] + 8 * h;
        const float4* xp0 = (const float4*)(xs[r] + p0 * XSTR);
        const float4* xp1 = (const float4*)(xs[r] + p1 * XSTR);
        #pragma unroll
        for (int c = 0; c < 16; c++) {
            float4 va = xp0[c];
            float4 vb = xp1[c];
            const float* av = (const float*)&va;
            const float* bv = (const float*)&vb;
            #pragma unroll
            for (int d = 0; d < 4; d++) {
                const float* qrow = qb + (4 * c + d) * QSTR;
                ulonglong2 q01 = *(const ulonglong2*)(qrow);       // j 8h..8h+3
                ulonglong2 q23 = *(const ulonglong2*)(qrow + 4);   // j 8h+4..8h+7
                unsigned long long xa = pk2(av[d], av[d]);
                unsigned long long xb = pk2(bv[d], bv[d]);
                fma2(accA[0], xa, q01.x); fma2(accA[1], xa, q01.y);
                fma2(accA[2], xa, q23.x); fma2(accA[3], xa, q23.y);
                fma2(accB[0], xb, q01.x); fma2(accB[1], xb, q01.y);
                fma2(accB[2], xb, q23.x); fma2(accB[3], xb, q23.y);
            }
        }
    }

    // ---- softmax over j: 8 in-thread + partner combine (xor 16) per patch ----
    const float* nev = ne_s[r] + 8 * h;
    float csum = 0.f;
    #pragma unroll
    for (int pp = 0; pp < 2; pp++) {
        const unsigned long long* acc = pp ? accB : accA;
        float u[8];
        #pragma unroll
        for (int m = 0; m < 4; m++) {
            float2 dv = unpk2(acc[m]);
            u[2 * m + 0] = nev[2 * m + 0] - dv.x;
            u[2 * m + 1] = nev[2 * m + 1] - dv.y;
        }
        float mx = u[0];
        #pragma unroll
        for (int j = 1; j < 8; j++) mx = fmaxf(mx, u[j]);
        mx = fmaxf(mx, __shfl_xor_sync(0xffffffffu, mx, 16));
        float E = 0.f, EU = 0.f;
        #pragma unroll
        for (int j = 0; j < 8; j++) {
            float e = __expf(u[j] - mx);
            E  += e;
            EU += e * u[j];
        }
        E  += __shfl_xor_sync(0xffffffffu, E, 16);
        EU += __shfl_xor_sync(0xffffffffu, EU, 16);
        if (h == 0) csum += __fdividef(EU, E);
    }

    // ---- reductions: warp -> CTA -> grid (deterministic) ----
    float my = csum + lse_part;
    #pragma unroll
    for (int o = 16; o; o >>= 1) my += __shfl_xor_sync(0xffffffffu, my, o);
    if (lane == 0) red[warp] = my;
    __syncthreads();
    if (t == 0) {
        g_blk_sum[blockIdx.x] = (red[0] + red[1]) + (red[2] + red[3]);
        __threadfence();
        unsigned prev = atomicAdd(&g_ctr, 1u);
        is_last_sh = (prev == NCTAS - 1);
    }
    __syncthreads();

    if (is_last_sh) {
        float s = 0.f;
        #pragma unroll 4
        for (int i = t; i < NCTAS; i += 128) s += g_blk_sum[i];
        #pragma unroll
        for (int o = 16; o; o >>= 1) s += __shfl_xor_sync(0xffffffffu, s, o);
        if (lane == 0) red[warp] = s;
        __syncthreads();
        if (t == 0) {
            out[0] = ((red[0] + red[1]) + (red[2] + red[3])) * (1.0f / (float)NROWS);
            g_ctr = 0;
        }
    }
}

extern "C" void kernel_launch(void* const* d_in, const int* in_sizes, int n_in,
                              void* d_out, int out_size) {
    const float* x = nullptr;
    const float* pred = nullptr;
    for (int i = 0; i < n_in; i++) {
        if (in_sizes[i] == 32 * 4096 * 128)      x    = (const float*)d_in[i];
        else if (in_sizes[i] == 32 * 1024 * 128) pred = (const float*)d_in[i];
    }
    kl_fused_kernel<<<NCTAS, 128>>>(x, pred, (float*)d_out);
}

// round 11
// speedup vs baseline: 1.0668x; 1.0668x over previous
#include <cuda_runtime.h>
#include <cuda_bf16.h>

// Shapes: batch_x [32,4096,128] -> N=4096 rows x 4096 (I=64 patches, L=64)
//         pred    [32,1024,128] -> N=4096 rows x 1024 (J=16 patches, L=64)
//
// Math (sum_l q_jl = 1 => lse_i cancels in softmax over j):
//   dot_ij = q_j . x_i (raw x);  u_ij = ne_j - dot_ij  (ne_j = sum q log q)
//   loss = mean_n [ sum_i ( sum_j softmax_j(u_ij)*u_ij + lse_i ) ]
//
// CTA = 128 threads = 2 rows x 2 warps/row. Phase A is a PURE copy stream
// (no math). Lane (g=lane&15, h=lane>>4) owns patches p0=32*wir+g, p1=p0+16
// and j-half h; it computes expsum (-> lse) in-thread for the ONE patch
// matching its h, so every patch's lse is computed exactly once with no
// shuffles. q transposed [l][j] stride 20, loaded as packed ulonglong2.
#define NROWS 4096
#define SEQ   4096
#define PREDL 1024
#define RPC   2
#define NCTAS (NROWS / RPC)   // 2048
#define XSTR  72
#define QSTR  20

__device__ float g_blk_sum[NCTAS];
__device__ unsigned g_ctr = 0;

__device__ __forceinline__ unsigned long long pk2(float a, float b) {
    unsigned long long r;
    asm("mov.b64 %0, {%1, %2};" : "=l"(r) : "f"(a), "f"(b));
    return r;
}
__device__ __forceinline__ void fma2(unsigned long long& d,
                                     unsigned long long a, unsigned long long b) {
    asm("fma.rn.f32x2 %0, %1, %2, %0;" : "+l"(d) : "l"(a), "l"(b));
}
__device__ __forceinline__ float2 unpk2(unsigned long long v) {
    float2 r;
    asm("mov.b64 {%0, %1}, %2;" : "=f"(r.x), "=f"(r.y) : "l"(v));
    return r;
}

__global__ __launch_bounds__(128, 4)
void kl_fused_kernel(const float* __restrict__ x, const float* __restrict__ pred,
                     float* __restrict__ out) {
    __shared__ __align__(16) float xs[RPC][64 * XSTR];   // 36.9KB
    __shared__ __align__(16) float qt[RPC][64 * QSTR];   // 10.2KB
    __shared__ __align__(16) float ne_s[RPC][16];
    __shared__ float red[4];
    __shared__ int   is_last_sh;

    const int t     = threadIdx.x;
    const int warp  = t >> 5;
    const int lane  = t & 31;
    const int r     = t >> 6;      // row within CTA
    const int tid64 = t & 63;      // thread within row group
    const int n     = blockIdx.x * RPC + r;

    // ---- Phase A: PURE coalesced copy x -> padded smem (no math) ----
    {
        const float4* x4 = (const float4*)(x + (size_t)n * SEQ);
        float* xb = xs[r];
        #pragma unroll
        for (int k = 0; k < 16; k++) {
            const int idx = tid64 + 64 * k;
            float4 v = x4[idx];
            ((float4*)(xb + (idx >> 4) * XSTR))[idx & 15] = v;
        }
    }

    // ---- Phase B: pred row -> q (smem, transposed [l][j]) + ne_j ----
    {
        const float4* pr4 = (const float4*)(pred + (size_t)n * PREDL);
        float* qb = qt[r];
        #pragma unroll
        for (int k = 0; k < 4; k++) {
            const int idx = tid64 + 64 * k;
            float4 v = pr4[idx];
            const int j  = idx >> 4;
            const int l0 = 4 * (idx & 15);
            // naive expsum (inputs ~N(0,1), fp32-safe; validated 1.2e-7)
            float e0 = __expf(v.x), e1 = __expf(v.y);
            float e2 = __expf(v.z), e3 = __expf(v.w);
            float E = e0 + e1 + e2 + e3;
            float S = e0 * v.x + e1 * v.y + e2 * v.z + e3 * v.w;
            #pragma unroll
            for (int o = 8; o; o >>= 1) {
                E += __shfl_xor_sync(0xffffffffu, E, o);
                S += __shfl_xor_sync(0xffffffffu, S, o);
            }
            float rinv = __frcp_rn(E);
            qb[(l0 + 0) * QSTR + j] = e0 * rinv;
            qb[(l0 + 1) * QSTR + j] = e1 * rinv;
            qb[(l0 + 2) * QSTR + j] = e2 * rinv;
            qb[(l0 + 3) * QSTR + j] = e3 * rinv;
            if ((lane & 15) == 0) ne_s[r][j] = S * rinv - __logf(E);
        }
    }
    __syncthreads();

    // ---- Phase C: 2 patches per lane (dots), own-h patch expsum in-thread ----
    const int g   = lane & 15;
    const int h   = lane >> 4;
    const int wir = warp & 1;
    const int p0  = 32 * wir + g;
    const int p1  = p0 + 16;

    unsigned long long accA[4], accB[4];
    #pragma unroll
    for (int m = 0; m < 4; m++) { accA[m] = 0ull; accB[m] = 0ull; }
    float Eown = 0.f;
    {
        const float* qb = qt[r] + 8 * h;
        const float4* xp0 = (const float4*)(xs[r] + p0 * XSTR);
        const float4* xp1 = (const float4*)(xs[r] + p1 * XSTR);
        #pragma unroll
        for (int c = 0; c < 16; c++) {
            float4 va = xp0[c];
            float4 vb = xp1[c];
            // expsum for the patch this lane owns (h=0 -> p0, h=1 -> p1)
            float4 ve;
            ve.x = h ? vb.x : va.x;  ve.y = h ? vb.y : va.y;
            ve.z = h ? vb.z : va.z;  ve.w = h ? vb.w : va.w;
            Eown += __expf(ve.x) + __expf(ve.y) + __expf(ve.z) + __expf(ve.w);
            const float* av = (const float*)&va;
            const float* bv = (const float*)&vb;
            #pragma unroll
            for (int d = 0; d < 4; d++) {
                const float* qrow = qb + (4 * c + d) * QSTR;
                ulonglong2 q01 = *(const ulonglong2*)(qrow);       // j 8h..8h+3
                ulonglong2 q23 = *(const ulonglong2*)(qrow + 4);   // j 8h+4..8h+7
                unsigned long long xa = pk2(av[d], av[d]);
                unsigned long long xb = pk2(bv[d], bv[d]);
                fma2(accA[0], xa, q01.x); fma2(accA[1], xa, q01.y);
                fma2(accA[2], xa, q23.x); fma2(accA[3], xa, q23.y);
                fma2(accB[0], xb, q01.x); fma2(accB[1], xb, q01.y);
                fma2(accB[2], xb, q23.x); fma2(accB[3], xb, q23.y);
            }
        }
    }
    float lse_part = __logf(Eown);   // each patch's lse computed exactly once

    // ---- softmax over j: 8 in-thread + partner combine (xor 16) per patch ----
    const float* nev = ne_s[r] + 8 * h;
    float csum = 0.f;
    #pragma unroll
    for (int pp = 0; pp < 2; pp++) {
        const unsigned long long* acc = pp ? accB : accA;
        float u[8];
        #pragma unroll
        for (int m = 0; m < 4; m++) {
            float2 dv = unpk2(acc[m]);
            u[2 * m + 0] = nev[2 * m + 0] - dv.x;
            u[2 * m + 1] = nev[2 * m + 1] - dv.y;
        }
        float mx = u[0];
        #pragma unroll
        for (int j = 1; j < 8; j++) mx = fmaxf(mx, u[j]);
        mx = fmaxf(mx, __shfl_xor_sync(0xffffffffu, mx, 16));
        float E = 0.f, EU = 0.f;
        #pragma unroll
        for (int j = 0; j < 8; j++) {
            float e = __expf(u[j] - mx);
            E  += e;
            EU += e * u[j];
        }
        E  += __shfl_xor_sync(0xffffffffu, E, 16);
        EU += __shfl_xor_sync(0xffffffffu, EU, 16);
        if (h == 0) csum += __fdividef(EU, E);
    }

    // ---- reductions: warp -> CTA -> grid (deterministic) ----
    float my = csum + lse_part;
    #pragma unroll
    for (int o = 16; o; o >>= 1) my += __shfl_xor_sync(0xffffffffu, my, o);
    if (lane == 0) red[warp] = my;
    __syncthreads();
    if (t == 0) {
        g_blk_sum[blockIdx.x] = (red[0] + red[1]) + (red[2] + red[3]);
        __threadfence();
        unsigned prev = atomicAdd(&g_ctr, 1u);
        is_last_sh = (prev == NCTAS - 1);
    }
    __syncthreads();

    if (is_last_sh) {
        float s = 0.f;
        #pragma unroll 4
        for (int i = t; i < NCTAS; i += 128) s += g_blk_sum[i];
        #pragma unroll
        for (int o = 16; o; o >>= 1) s += __shfl_xor_sync(0xffffffffu, s, o);
        if (lane == 0) red[warp] = s;
        __syncthreads();
        if (t == 0) {
            out[0] = ((red[0] + red[1]) + (red[2] + red[3])) * (1.0f / (float)NROWS);
            g_ctr = 0;
        }
    }
}

extern "C" void kernel_launch(void* const* d_in, const int* in_sizes, int n_in,
                              void* d_out, int out_size) {
    const float* x = nullptr;
    const float* pred = nullptr;
    for (int i = 0; i < n_in; i++) {
        if (in_sizes[i] == 32 * 4096 * 128)      x    = (const float*)d_in[i];
        else if (in_sizes[i] == 32 * 1024 * 128) pred = (const float*)d_in[i];
    }
    kl_fused_kernel<<<NCTAS, 128>>>(x, pred, (float*)d_out);
}

// round 12
// speedup vs baseline: 1.4766x; 1.3842x over previous
#include <cuda_runtime.h>
#include <cuda_bf16.h>
#include <cstdint>

// Shapes: batch_x [32,4096,128] -> N=4096 rows x 4096 (I=64 patches, L=64)
//         pred    [32,1024,128] -> N=4096 rows x 1024 (J=16 patches, L=64)
//
// Math (sum_l q_jl = 1 => lse_i cancels in softmax over j):
//   dot_ij = q_j . x_i (raw x);  u_ij = ne_j - dot_ij  (ne_j = sum q log q)
//   loss = mean_n [ sum_i ( sum_j softmax_j(u_ij)*u_ij + lse_i ) ]
//
// Tensor-core version: per row, D[64x16] = X[64x64] * Q^T via
// mma.sync.m16n8k8.row.col.f32.tf32.tf32.f32 (tf32 by HW truncation of f32
// bits; lse uses the exact f32 smem so only the GEMM sees tf32).
// CTA = 128 thr = 2 rows x 2 warps/row; warp covers 2 m-tiles (32 patches).
// x smem [patch][68]  -> A-fragment LDS.32 conflict-free (68 = 4 mod 32)
// q smem [j][68]      -> B-fragment LDS.32 conflict-free, natural stores
#define NROWS 4096
#define SEQ   4096
#define PREDL 1024
#define RPC   2
#define NCTAS (NROWS / RPC)   // 2048
#define XSTR  68
#define QSTR  68

__device__ float g_blk_sum[NCTAS];
__device__ unsigned g_ctr = 0;

__device__ __forceinline__ void mma_tf32(float d[4],
                                         uint32_t a0, uint32_t a1,
                                         uint32_t a2, uint32_t a3,
                                         uint32_t b0, uint32_t b1) {
    asm volatile(
        "mma.sync.aligned.m16n8k8.row.col.f32.tf32.tf32.f32 "
        "{%0,%1,%2,%3}, {%4,%5,%6,%7}, {%8,%9}, {%0,%1,%2,%3};"
        : "+f"(d[0]), "+f"(d[1]), "+f"(d[2]), "+f"(d[3])
        : "r"(a0), "r"(a1), "r"(a2), "r"(a3), "r"(b0), "r"(b1));
}

__global__ __launch_bounds__(128, 5)
void kl_fused_kernel(const float* __restrict__ x, const float* __restrict__ pred,
                     float* __restrict__ out) {
    __shared__ __align__(16) float xs[RPC][64 * XSTR];   // 34.8KB
    __shared__ __align__(16) float qs[RPC][16 * QSTR];   // 8.7KB
    __shared__ __align__(16) float ne_s[RPC][16];
    __shared__ float red[4];
    __shared__ int   is_last_sh;

    const int t     = threadIdx.x;
    const int warp  = t >> 5;
    const int lane  = t & 31;
    const int r     = t >> 6;      // row within CTA
    const int tid64 = t & 63;
    const int n     = blockIdx.x * RPC + r;

    // ---- Phase A: PURE coalesced copy x -> smem [patch][68] ----
    {
        const float4* x4 = (const float4*)(x + (size_t)n * SEQ);
        float* xb = xs[r];
        #pragma unroll
        for (int k = 0; k < 16; k++) {
            const int idx = tid64 + 64 * k;
            float4 v = x4[idx];
            ((float4*)(xb + (idx >> 4) * XSTR))[idx & 15] = v;
        }
    }

    // ---- Phase B: pred row -> q smem [j][68] + ne_j ----
    {
        const float4* pr4 = (const float4*)(pred + (size_t)n * PREDL);
        float* qb = qs[r];
        #pragma unroll
        for (int k = 0; k < 4; k++) {
            const int idx = tid64 + 64 * k;
            float4 v = pr4[idx];
            const int j = idx >> 4;
            // naive expsum (inputs ~N(0,1), fp32-safe; validated 1.2e-7)
            float e0 = __expf(v.x), e1 = __expf(v.y);
            float e2 = __expf(v.z), e3 = __expf(v.w);
            float E = e0 + e1 + e2 + e3;
            float S = e0 * v.x + e1 * v.y + e2 * v.z + e3 * v.w;
            #pragma unroll
            for (int o = 8; o; o >>= 1) {
                E += __shfl_xor_sync(0xffffffffu, E, o);
                S += __shfl_xor_sync(0xffffffffu, S, o);
            }
            float rinv = __frcp_rn(E);
            ((float4*)(qb + j * QSTR))[idx & 15] =
                make_float4(e0 * rinv, e1 * rinv, e2 * rinv, e3 * rinv);
            if ((lane & 15) == 0) ne_s[r][j] = S * rinv - __logf(E);
        }
    }
    __syncthreads();

    // ---- Phase C: tensor-core GEMM (warp covers patches mb..mb+31) ----
    const int wir  = warp & 1;
    const int gid  = lane >> 2;   // groupID
    const int tid4 = lane & 3;    // threadID_in_group
    const int mb   = 32 * wir;

    const uint32_t* xu = (const uint32_t*)xs[r];
    const uint32_t* qu = (const uint32_t*)qs[r];

    float d[2][2][4];             // [m-tile][n-tile][reg]
    #pragma unroll
    for (int mt = 0; mt < 2; mt++)
        #pragma unroll
        for (int nt = 0; nt < 2; nt++)
            #pragma unroll
            for (int rg = 0; rg < 4; rg++) d[mt][nt][rg] = 0.f;

    #pragma unroll
    for (int kt = 0; kt < 8; kt++) {
        const int c = 8 * kt + tid4;
        // B fragments: b0=(k=tid4,n=gid), b1=(k=tid4+4,n=gid); B[k][n]=q[n][k]
        uint32_t b00 = qu[gid * QSTR + c];
        uint32_t b01 = qu[gid * QSTR + c + 4];
        uint32_t b10 = qu[(8 + gid) * QSTR + c];
        uint32_t b11 = qu[(8 + gid) * QSTR + c + 4];
        #pragma unroll
        for (int mt = 0; mt < 2; mt++) {
            const int rowb = (mb + 16 * mt + gid) * XSTR;
            uint32_t a0 = xu[rowb + c];                 // (g,   t)
            uint32_t a1 = xu[rowb + 8 * XSTR + c];      // (g+8, t)
            uint32_t a2 = xu[rowb + c + 4];             // (g,   t+4)
            uint32_t a3 = xu[rowb + 8 * XSTR + c + 4];  // (g+8, t+4)
            mma_tf32(d[mt][0], a0, a1, a2, a3, b00, b01);
            mma_tf32(d[mt][1], a0, a1, a2, a3, b10, b11);
        }
    }

    // ---- softmax over j per patch row (4 u in-thread + shfl over tid4) ----
    // D lane mapping: rows gid(+8), cols 2*tid4(+1) per n-tile.
    const float ne0 = ne_s[r][2 * tid4];
    const float ne1 = ne_s[r][2 * tid4 + 1];
    const float ne2 = ne_s[r][8 + 2 * tid4];
    const float ne3 = ne_s[r][8 + 2 * tid4 + 1];
    float csum = 0.f;
    #pragma unroll
    for (int mt = 0; mt < 2; mt++) {
        #pragma unroll
        for (int half = 0; half < 2; half++) {
            float u0 = ne0 - d[mt][0][2 * half + 0];
            float u1 = ne1 - d[mt][0][2 * half + 1];
            float u2 = ne2 - d[mt][1][2 * half + 0];
            float u3 = ne3 - d[mt][1][2 * half + 1];
            float mx = fmaxf(fmaxf(u0, u1), fmaxf(u2, u3));
            mx = fmaxf(mx, __shfl_xor_sync(0xffffffffu, mx, 1));
            mx = fmaxf(mx, __shfl_xor_sync(0xffffffffu, mx, 2));
            float e0 = __expf(u0 - mx), e1 = __expf(u1 - mx);
            float e2 = __expf(u2 - mx), e3 = __expf(u3 - mx);
            float E  = e0 + e1 + e2 + e3;
            float EU = e0 * u0 + e1 * u1 + e2 * u2 + e3 * u3;
            E  += __shfl_xor_sync(0xffffffffu, E, 1);
            EU += __shfl_xor_sync(0xffffffffu, EU, 1);
            E  += __shfl_xor_sync(0xffffffffu, E, 2);
            EU += __shfl_xor_sync(0xffffffffu, EU, 2);
            if (tid4 == 0) csum += __fdividef(EU, E);
        }
    }

    // ---- lse: lane owns patch mb+lane; exact f32 from smem, in-thread ----
    float Eown = 0.f;
    {
        const float4* xp4 = (const float4*)(xs[r] + (mb + lane) * XSTR);
        #pragma unroll
        for (int c = 0; c < 16; c++) {
            float4 v = xp4[c];
            Eown += __expf(v.x) + __expf(v.y) + __expf(v.z) + __expf(v.w);
        }
    }
    float my = csum + __logf(Eown);

    // ---- reductions: warp -> CTA -> grid (deterministic) ----
    #pragma unroll
    for (int o = 16; o; o >>= 1) my += __shfl_xor_sync(0xffffffffu, my, o);
    if (lane == 0) red[warp] = my;
    __syncthreads();
    if (t == 0) {
        g_blk_sum[blockIdx.x] = (red[0] + red[1]) + (red[2] + red[3]);
        __threadfence();
        unsigned prev = atomicAdd(&g_ctr, 1u);
        is_last_sh = (prev == NCTAS - 1);
    }
    __syncthreads();

    if (is_last_sh) {
        float s = 0.f;
        #pragma unroll 4
        for (int i = t; i < NCTAS; i += 128) s += g_blk_sum[i];
        #pragma unroll
        for (int o = 16; o; o >>= 1) s += __shfl_xor_sync(0xffffffffu, s, o);
        if (lane == 0) red[warp] = s;
        __syncthreads();
        if (t == 0) {
            out[0] = ((red[0] + red[1]) + (red[2] + red[3])) * (1.0f / (float)NROWS);
            g_ctr = 0;
        }
    }
}

extern "C" void kernel_launch(void* const* d_in, const int* in_sizes, int n_in,
                              void* d_out, int out_size) {
    const float* x = nullptr;
    const float* pred = nullptr;
    for (int i = 0; i < n_in; i++) {
        if (in_sizes[i] == 32 * 4096 * 128)      x    = (const float*)d_in[i];
        else if (in_sizes[i] == 32 * 1024 * 128) pred = (const float*)d_in[i];
    }
    kl_fused_kernel<<<NCTAS, 128>>>(x, pred, (float*)d_out);
}

// round 13
// speedup vs baseline: 1.5891x; 1.0762x over previous
#include <cuda_runtime.h>
#include <cuda_bf16.h>
#include <cstdint>

// Shapes: batch_x [32,4096,128] -> N=4096 rows x 4096 (I=64 patches, L=64)
//         pred    [32,1024,128] -> N=4096 rows x 1024 (J=16 patches, L=64)
//
// Math (sum_l q_jl = 1 => lse_i cancels in softmax over j):
//   dot_ij = q_j . x_i (raw x);  u_ij = ne_j - dot_ij  (ne_j = sum q log q)
//   loss = mean_n [ sum_i ( sum_j softmax_j(u_ij)*u_ij + lse_i ) ]
//
// Tensor-core version (m16n8k8 tf32), with the x GMEM->SMEM copy issued as
// cp.async so it overlaps phase B's pred softmax; wait only at the barrier
// before the MMA. lse uses exact f32 smem (only the GEMM sees tf32).
#define NROWS 4096
#define SEQ   4096
#define PREDL 1024
#define RPC   2
#define NCTAS (NROWS / RPC)   // 2048
#define XSTR  68
#define QSTR  68

__device__ float g_blk_sum[NCTAS];
__device__ unsigned g_ctr = 0;

__device__ __forceinline__ void mma_tf32(float d[4],
                                         uint32_t a0, uint32_t a1,
                                         uint32_t a2, uint32_t a3,
                                         uint32_t b0, uint32_t b1) {
    asm volatile(
        "mma.sync.aligned.m16n8k8.row.col.f32.tf32.tf32.f32 "
        "{%0,%1,%2,%3}, {%4,%5,%6,%7}, {%8,%9}, {%0,%1,%2,%3};"
        : "+f"(d[0]), "+f"(d[1]), "+f"(d[2]), "+f"(d[3])
        : "r"(a0), "r"(a1), "r"(a2), "r"(a3), "r"(b0), "r"(b1));
}

__device__ __forceinline__ void cp_async16(uint32_t smem_addr, const void* gptr) {
    asm volatile("cp.async.ca.shared.global [%0], [%1], 16;"
                 :: "r"(smem_addr), "l"(gptr));
}

__global__ __launch_bounds__(128, 5)
void kl_fused_kernel(const float* __restrict__ x, const float* __restrict__ pred,
                     float* __restrict__ out) {
    __shared__ __align__(16) float xs[RPC][64 * XSTR];   // 34.8KB
    __shared__ __align__(16) float qs[RPC][16 * QSTR];   // 8.7KB
    __shared__ __align__(16) float ne_s[RPC][16];
    __shared__ float red[4];
    __shared__ int   is_last_sh;

    const int t     = threadIdx.x;
    const int warp  = t >> 5;
    const int lane  = t & 31;
    const int r     = t >> 6;      // row within CTA
    const int tid64 = t & 63;
    const int n     = blockIdx.x * RPC + r;

    // ---- Phase A: x -> smem via cp.async (overlaps with phase B) ----
    {
        const float4* x4 = (const float4*)(x + (size_t)n * SEQ);
        float* xb = xs[r];
        #pragma unroll
        for (int k = 0; k < 16; k++) {
            const int idx = tid64 + 64 * k;
            uint32_t dst = (uint32_t)__cvta_generic_to_shared(
                (float4*)(xb + (idx >> 4) * XSTR) + (idx & 15));
            cp_async16(dst, x4 + idx);
        }
        asm volatile("cp.async.commit_group;" ::: "memory");
    }

    // ---- Phase B: pred row -> q smem [j][68] + ne_j (x loads in flight) ----
    {
        const float4* pr4 = (const float4*)(pred + (size_t)n * PREDL);
        float* qb = qs[r];
        #pragma unroll
        for (int k = 0; k < 4; k++) {
            const int idx = tid64 + 64 * k;
            float4 v = pr4[idx];
            const int j = idx >> 4;
            // naive expsum (inputs ~N(0,1), fp32-safe; validated 1.2e-7)
            float e0 = __expf(v.x), e1 = __expf(v.y);
            float e2 = __expf(v.z), e3 = __expf(v.w);
            float E = e0 + e1 + e2 + e3;
            float S = e0 * v.x + e1 * v.y + e2 * v.z + e3 * v.w;
            #pragma unroll
            for (int o = 8; o; o >>= 1) {
                E += __shfl_xor_sync(0xffffffffu, E, o);
                S += __shfl_xor_sync(0xffffffffu, S, o);
            }
            float rinv = __frcp_rn(E);
            ((float4*)(qb + j * QSTR))[idx & 15] =
                make_float4(e0 * rinv, e1 * rinv, e2 * rinv, e3 * rinv);
            if ((lane & 15) == 0) ne_s[r][j] = S * rinv - __logf(E);
        }
    }
    asm volatile("cp.async.wait_group 0;" ::: "memory");
    __syncthreads();

    // ---- Phase C: tensor-core GEMM (warp covers patches mb..mb+31) ----
    const int wir  = warp & 1;
    const int gid  = lane >> 2;   // groupID
    const int tid4 = lane & 3;    // threadID_in_group
    const int mb   = 32 * wir;

    const uint32_t* xu = (const uint32_t*)xs[r];
    const uint32_t* qu = (const uint32_t*)qs[r];

    float d[2][2][4];             // [m-tile][n-tile][reg]
    #pragma unroll
    for (int mt = 0; mt < 2; mt++)
        #pragma unroll
        for (int nt = 0; nt < 2; nt++)
            #pragma unroll
            for (int rg = 0; rg < 4; rg++) d[mt][nt][rg] = 0.f;

    #pragma unroll
    for (int kt = 0; kt < 8; kt++) {
        const int c = 8 * kt + tid4;
        uint32_t b00 = qu[gid * QSTR + c];
        uint32_t b01 = qu[gid * QSTR + c + 4];
        uint32_t b10 = qu[(8 + gid) * QSTR + c];
        uint32_t b11 = qu[(8 + gid) * QSTR + c + 4];
        #pragma unroll
        for (int mt = 0; mt < 2; mt++) {
            const int rowb = (mb + 16 * mt + gid) * XSTR;
            uint32_t a0 = xu[rowb + c];
            uint32_t a1 = xu[rowb + 8 * XSTR + c];
            uint32_t a2 = xu[rowb + c + 4];
            uint32_t a3 = xu[rowb + 8 * XSTR + c + 4];
            mma_tf32(d[mt][0], a0, a1, a2, a3, b00, b01);
            mma_tf32(d[mt][1], a0, a1, a2, a3, b10, b11);
        }
    }

    // ---- softmax over j per patch row (4 u in-thread + shfl over tid4) ----
    const float ne0 = ne_s[r][2 * tid4];
    const float ne1 = ne_s[r][2 * tid4 + 1];
    const float ne2 = ne_s[r][8 + 2 * tid4];
    const float ne3 = ne_s[r][8 + 2 * tid4 + 1];
    float csum = 0.f;
    #pragma unroll
    for (int mt = 0; mt < 2; mt++) {
        #pragma unroll
        for (int half = 0; half < 2; half++) {
            float u0 = ne0 - d[mt][0][2 * half + 0];
            float u1 = ne1 - d[mt][0][2 * half + 1];
            float u2 = ne2 - d[mt][1][2 * half + 0];
            float u3 = ne3 - d[mt][1][2 * half + 1];
            float mx = fmaxf(fmaxf(u0, u1), fmaxf(u2, u3));
            mx = fmaxf(mx, __shfl_xor_sync(0xffffffffu, mx, 1));
            mx = fmaxf(mx, __shfl_xor_sync(0xffffffffu, mx, 2));
            float e0 = __expf(u0 - mx), e1 = __expf(u1 - mx);
            float e2 = __expf(u2 - mx), e3 = __expf(u3 - mx);
            float E  = e0 + e1 + e2 + e3;
            float EU = e0 * u0 + e1 * u1 + e2 * u2 + e3 * u3;
            E  += __shfl_xor_sync(0xffffffffu, E, 1);
            EU += __shfl_xor_sync(0xffffffffu, EU, 1);
            E  += __shfl_xor_sync(0xffffffffu, E, 2);
            EU += __shfl_xor_sync(0xffffffffu, EU, 2);
            if (tid4 == 0) csum += __fdividef(EU, E);
        }
    }

    // ---- lse: lane owns patch mb+lane; exact f32 from smem, in-thread ----
    float Eown = 0.f;
    {
        const float4* xp4 = (const float4*)(xs[r] + (mb + lane) * XSTR);
        #pragma unroll
        for (int c = 0; c < 16; c++) {
            float4 v = xp4[c];
            Eown += __expf(v.x) + __expf(v.y) + __expf(v.z) + __expf(v.w);
        }
    }
    float my = csum + __logf(Eown);

    // ---- reductions: warp -> CTA -> grid (deterministic) ----
    #pragma unroll
    for (int o = 16; o; o >>= 1) my += __shfl_xor_sync(0xffffffffu, my, o);
    if (lane == 0) red[warp] = my;
    __syncthreads();
    if (t == 0) {
        g_blk_sum[blockIdx.x] = (red[0] + red[1]) + (red[2] + red[3]);
        __threadfence();
        unsigned prev = atomicAdd(&g_ctr, 1u);
        is_last_sh = (prev == NCTAS - 1);
    }
    __syncthreads();

    if (is_last_sh) {
        float s = 0.f;
        #pragma unroll 4
        for (int i = t; i < NCTAS; i += 128) s += g_blk_sum[i];
        #pragma unroll
        for (int o = 16; o; o >>= 1) s += __shfl_xor_sync(0xffffffffu, s, o);
        if (lane == 0) red[warp] = s;
        __syncthreads();
        if (t == 0) {
            out[0] = ((red[0] + red[1]) + (red[2] + red[3])) * (1.0f / (float)NROWS);
            g_ctr = 0;
        }
    }
}

extern "C" void kernel_launch(void* const* d_in, const int* in_sizes, int n_in,
                              void* d_out, int out_size) {
    const float* x = nullptr;
    const float* pred = nullptr;
    for (int i = 0; i < n_in; i++) {
        if (in_sizes[i] == 32 * 4096 * 128)      x    = (const float*)d_in[i];
        else if (in_sizes[i] == 32 * 1024 * 128) pred = (const float*)d_in[i];
    }
    kl_fused_kernel<<<NCTAS, 128>>>(x, pred, (float*)d_out);
}